// round 7
// baseline (speedup 1.0000x reference)
#include <cuda_runtime.h>
#include <math.h>

// Problem dims
#define B_ 8
#define L_ 512
#define D_ 512
#define H_ 8
#define DH_ 64
#define NROWS 4096          // B*L
#define NPAD 1664           // 512(q)+512(k)+512(v)+24(p) padded

// Output layout (concatenated fp32): readout | state_seq | mom_seq
#define OFF_S 2097152UL
#define OFF_M 136314880UL

// Packed per-(b,h) stream: [q(64) | k_norm(64) | v(64) | gates(4)] per step
#define PSTEP 196

// Scratch (static device arrays — no allocation)
__device__ float g_W[D_ * NPAD];                       // packed [Wq|Wk|Wv|Wp|0pad]
__device__ float g_out[(size_t)NROWS * NPAD];          // raw projections
__device__ float g_pack[(size_t)B_ * H_ * L_ * PSTEP]; // packed recurrence stream

// ---------------------------------------------------------------------------
// Kernel 1: pack weights into one [512 x 1664] matrix (zero-padded)
// ---------------------------------------------------------------------------
__global__ void pack_weights_kernel(const float* __restrict__ Wq,
                                    const float* __restrict__ Wk,
                                    const float* __restrict__ Wv,
                                    const float* __restrict__ Wp) {
    int idx = blockIdx.x * blockDim.x + threadIdx.x;
    if (idx >= D_ * NPAD) return;
    int d = idx / NPAD;
    int n = idx - d * NPAD;
    float v = 0.f;
    if (n < 512)       v = Wq[d * 512 + n];
    else if (n < 1024) v = Wk[d * 512 + (n - 512)];
    else if (n < 1536) v = Wv[d * 512 + (n - 1024)];
    else if (n < 1560) v = Wp[d * 24 + (n - 1536)];
    g_W[idx] = v;
}

// ---------------------------------------------------------------------------
// Kernel 2: SGEMM  C[4096,1664] = A[4096,512] * W[512,1664]
// 128x128 tile, BK=8, 256 threads, 8x8 per thread
// ---------------------------------------------------------------------------
__global__ __launch_bounds__(256) void sgemm_kernel(const float* __restrict__ A) {
    __shared__ float As[8][128];
    __shared__ float Bs[8][128];
    const int tid  = threadIdx.x;
    const int brow = blockIdx.y * 128;
    const int bcol = blockIdx.x * 128;
    const int arow = tid >> 1, acol = (tid & 1) * 4;
    const int bro  = tid >> 5, bco  = (tid & 31) * 4;
    const int tx   = tid & 15, ty   = tid >> 4;

    float acc[8][8];
#pragma unroll
    for (int i = 0; i < 8; i++)
#pragma unroll
        for (int j = 0; j < 8; j++) acc[i][j] = 0.f;

    const float* Ap = A + (size_t)(brow + arow) * D_ + acol;
    const float* Bp = g_W + (size_t)bro * NPAD + bcol + bco;

    for (int k0 = 0; k0 < D_; k0 += 8) {
        float4 av = *(const float4*)Ap;
        float4 bv = *(const float4*)Bp;
        As[acol + 0][arow] = av.x;
        As[acol + 1][arow] = av.y;
        As[acol + 2][arow] = av.z;
        As[acol + 3][arow] = av.w;
        *(float4*)&Bs[bro][bco] = bv;
        __syncthreads();
#pragma unroll
        for (int kk = 0; kk < 8; kk++) {
            float ra[8], rb[8];
            *(float4*)&ra[0] = *(const float4*)&As[kk][ty * 8];
            *(float4*)&ra[4] = *(const float4*)&As[kk][ty * 8 + 4];
            *(float4*)&rb[0] = *(const float4*)&Bs[kk][tx * 8];
            *(float4*)&rb[4] = *(const float4*)&Bs[kk][tx * 8 + 4];
#pragma unroll
            for (int i = 0; i < 8; i++)
#pragma unroll
                for (int j = 0; j < 8; j++)
                    acc[i][j] = fmaf(ra[i], rb[j], acc[i][j]);
        }
        __syncthreads();
        Ap += 8;
        Bp += 8 * NPAD;
    }

    float* Cp = g_out + (size_t)(brow + ty * 8) * NPAD + bcol + tx * 8;
#pragma unroll
    for (int i = 0; i < 8; i++) {
        *(float4*)(Cp + 0) = make_float4(acc[i][0], acc[i][1], acc[i][2], acc[i][3]);
        *(float4*)(Cp + 4) = make_float4(acc[i][4], acc[i][5], acc[i][6], acc[i][7]);
        Cp += NPAD;
    }
}

// ---------------------------------------------------------------------------
// Kernel 3: postproc — normalize k, compute gates, repack into per-(b,h)
// contiguous stream g_pack[b][h][l] = [q64 | k64 | v64 | a,e,th,0]
// ---------------------------------------------------------------------------
__global__ __launch_bounds__(64) void postproc_kernel(const float* __restrict__ bp) {
    const int row = blockIdx.x;
    const int b = row >> 9, l = row & 511;
    const float* base = g_out + (size_t)row * NPAD;
    const int t  = threadIdx.x;
    const int hh = t >> 3, e8 = t & 7;

    __shared__ float sg[24];
    if (t < 24) {
        float p = base[1536 + t] + bp[t];
        sg[t] = (t < 16) ? (1.0f / (1.0f + expf(-p)))
                         : ((p > 20.f) ? p : log1pf(expf(p)));
    }

    float* dst = g_pack + ((size_t)(b * 8 + hh) * 512 + l) * PSTEP;

    // k: normalize and write
    float kv[8];
    const float* kb = base + 512 + hh * 64 + e8 * 8;
    *(float4*)&kv[0] = *(const float4*)(kb + 0);
    *(float4*)&kv[4] = *(const float4*)(kb + 4);
    float ss = 0.f;
#pragma unroll
    for (int u = 0; u < 8; u++) ss = fmaf(kv[u], kv[u], ss);
    ss += __shfl_xor_sync(0xffffffffu, ss, 1);
    ss += __shfl_xor_sync(0xffffffffu, ss, 2);
    ss += __shfl_xor_sync(0xffffffffu, ss, 4);
    float scale = 1.0f / fmaxf(sqrtf(ss), 1e-12f);
#pragma unroll
    for (int u = 0; u < 8; u++) kv[u] *= scale;
    *(float4*)(dst + 64 + e8 * 8 + 0) = *(float4*)&kv[0];
    *(float4*)(dst + 64 + e8 * 8 + 4) = *(float4*)&kv[4];

    // q copy
    const float* qb = base + hh * 64 + e8 * 8;
    *(float4*)(dst + e8 * 8 + 0) = *(const float4*)(qb + 0);
    *(float4*)(dst + e8 * 8 + 4) = *(const float4*)(qb + 4);

    // v copy
    const float* vb = base + 1024 + hh * 64 + e8 * 8;
    *(float4*)(dst + 128 + e8 * 8 + 0) = *(const float4*)(vb + 0);
    *(float4*)(dst + 128 + e8 * 8 + 4) = *(const float4*)(vb + 4);

    __syncthreads();
    if (e8 < 4) dst[192 + e8] = (e8 < 3) ? sg[e8 * 8 + hh] : 0.f;
}

// ---------------------------------------------------------------------------
// Kernel 4: recurrence. grid = B*H*16 = 1024 CTAs x 128 threads (4096 warps).
// CTA handles 4 rows of one (b,h); each warp = one state row; lane c owns
// 2 columns (s[2], m[2] in registers). 5-round full-warp shfl reductions.
// 4-deep register ring with prefetch distance 3 covers L2/DRAM latency.
// ---------------------------------------------------------------------------
__global__ __launch_bounds__(128) void recurrence_kernel(const float* __restrict__ prev_state,
                                                         const float* __restrict__ prev_mom,
                                                         float* __restrict__ out) {
    const int bid = blockIdx.x;
    const int rb  = bid & 15;
    const int h   = (bid >> 4) & 7;
    const int b   = bid >> 7;
    const int t   = threadIdx.x;
    const int r = t >> 5, c = t & 31;
    const int gi = rb * 4 + r;                  // global state row in [0,64)

    float s[2], m[2];
    {
        const size_t off = ((size_t)((b * 8 + h) * 64 + gi)) * 64 + c * 2;
        float2 sv = *(const float2*)(prev_state + off);
        float2 mv = *(const float2*)(prev_mom + off);
        s[0] = sv.x; s[1] = sv.y;
        m[0] = mv.x; m[1] = mv.y;
    }

    const float* pbh = g_pack + (size_t)((b * 8 + h) * 512) * PSTEP;
    float* ro  = out + ((size_t)(b * 512) * 8 + h) * 64 + gi;
    float* ssq = out + OFF_S + ((size_t)(b * 512) * 8 + h) * 4096 + (size_t)gi * 64 + c * 2;
    float* msq = ssq + (OFF_M - OFF_S);

    // 4-deep prefetch ring (q, k, v, gates)
    float2 qb[4], kb[4];
    float vb[4];
    float4 gb[4];
#pragma unroll
    for (int p = 0; p < 3; p++) {
        const float* sp = pbh + p * PSTEP;
        qb[p] = *(const float2*)(sp + c * 2);
        kb[p] = *(const float2*)(sp + 64 + c * 2);
        vb[p] = sp[128 + gi];
        gb[p] = *(const float4*)(sp + 192);
    }

#pragma unroll 4
    for (int l = 0; l < 512; ++l) {
        const int bi = l & 3;
        const int pi = (l + 3) & 3;
        const int pl = (l + 3 < 512) ? (l + 3) : 511;
        const float* sp = pbh + (size_t)pl * PSTEP;
        // prefetch step l+3 into ring slot pi (never collides with bi)
        qb[pi] = *(const float2*)(sp + c * 2);
        kb[pi] = *(const float2*)(sp + 64 + c * 2);
        vb[pi] = sp[128 + gi];
        gb[pi] = *(const float4*)(sp + 192);

        // partial dot products over owned 2 columns
        float pv = fmaf(s[1], kb[bi].y, s[0] * kb[bi].x);
        float py = fmaf(s[1], qb[bi].y, s[0] * qb[bi].x);

        // reduce over the 32 lanes of this row (pv/py chains interleave)
        pv += __shfl_xor_sync(0xffffffffu, pv, 1);
        py += __shfl_xor_sync(0xffffffffu, py, 1);
        pv += __shfl_xor_sync(0xffffffffu, pv, 2);
        py += __shfl_xor_sync(0xffffffffu, py, 2);
        pv += __shfl_xor_sync(0xffffffffu, pv, 4);
        py += __shfl_xor_sync(0xffffffffu, py, 4);
        pv += __shfl_xor_sync(0xffffffffu, pv, 8);
        py += __shfl_xor_sync(0xffffffffu, py, 8);
        pv += __shfl_xor_sync(0xffffffffu, pv, 16);
        py += __shfl_xor_sync(0xffffffffu, py, 16);

        if (c == 0) __stcs(ro + (size_t)l * 512, py);   // readout: PRE-update state

        const float d   = pv - vb[bi];
        const float td  = gb[bi].z * d;
        const float oma = 1.0f - gb[bi].x;
        const float e   = gb[bi].y;
        m[0] = fmaf(e, m[0], -td * kb[bi].x);   // eta*mom - theta*grad
        m[1] = fmaf(e, m[1], -td * kb[bi].y);
        s[0] = fmaf(oma, s[0], m[0]);           // (1-alpha)*state + mom
        s[1] = fmaf(oma, s[1], m[1]);

        __stcs((float2*)(ssq + (size_t)l * 32768), make_float2(s[0], s[1]));
        __stcs((float2*)(msq + (size_t)l * 32768), make_float2(m[0], m[1]));
    }
}

// ---------------------------------------------------------------------------
// Launch
// ---------------------------------------------------------------------------
extern "C" void kernel_launch(void* const* d_in, const int* in_sizes, int n_in,
                              void* d_out, int out_size) {
    const float* inputs   = (const float*)d_in[0];
    const float* Wq       = (const float*)d_in[1];
    const float* Wk       = (const float*)d_in[2];
    const float* Wv       = (const float*)d_in[3];
    const float* Wp       = (const float*)d_in[4];
    const float* bp       = (const float*)d_in[5];
    const float* prev_st  = (const float*)d_in[6];
    const float* prev_mom = (const float*)d_in[7];
    float* out = (float*)d_out;

    pack_weights_kernel<<<(D_ * NPAD + 255) / 256, 256>>>(Wq, Wk, Wv, Wp);
    sgemm_kernel<<<dim3(NPAD / 128, NROWS / 128), 256>>>(inputs);
    postproc_kernel<<<NROWS, 64>>>(bp);
    recurrence_kernel<<<B_ * H_ * 16, 128>>>(prev_st, prev_mom, out);
}